// round 13
// baseline (speedup 1.0000x reference)
#include <cuda_runtime.h>
#include <cuda_fp16.h>
#include <math.h>
#include <stdint.h>

#define B_ 16
#define C_ 64
#define HW_ 64
#define E_ 16
#define KTOP_ 4

// ------------------------- scratch (device globals) -------------------------
__device__ float g_rowsum[B_ * 64 * C_];            // [b][row][ci] exact fp32
__device__ int   g_cnt = 0;                         // xconv-done counter
__device__ float g_beff[B_ * C_];
__device__ __half g_Whi[B_ * 9 * C_ * C_];          // [b][tap][co][ci]
__device__ __half g_xT[(size_t)B_ * 66 * 66 * C_];  // [b][rp][cp][ci]

// ------------------------- helpers ------------------------------------------
__device__ __forceinline__ uint32_t smem_u32(const void* p) {
    uint32_t a;
    asm("{ .reg .u64 t; cvta.to.shared.u64 t, %1; cvt.u32.u64 %0, t; }" : "=r"(a) : "l"(p));
    return a;
}
__device__ __forceinline__ void ldsm_x4(uint32_t* r, uint32_t addr) {
    asm volatile("ldmatrix.sync.aligned.m8n8.x4.shared.b16 {%0,%1,%2,%3}, [%4];"
        : "=r"(r[0]), "=r"(r[1]), "=r"(r[2]), "=r"(r[3]) : "r"(addr));
}
__device__ __forceinline__ void mma16816(float* d, const uint32_t* a, const uint32_t* b) {
    asm volatile(
        "mma.sync.aligned.m16n8k16.row.col.f32.f16.f16.f32 "
        "{%0,%1,%2,%3}, {%4,%5,%6,%7}, {%8,%9}, {%0,%1,%2,%3};"
        : "+f"(d[0]), "+f"(d[1]), "+f"(d[2]), "+f"(d[3])
        : "r"(a[0]), "r"(a[1]), "r"(a[2]), "r"(a[3]), "r"(b[0]), "r"(b[1]));
}
__device__ __forceinline__ void cp_async16(uint32_t dst, const void* src) {
    asm volatile("cp.async.cg.shared.global [%0], [%1], 16;" :: "r"(dst), "l"(src));
}
#define CP_COMMIT() asm volatile("cp.async.commit_group;" ::: "memory")
#define CP_WAIT0()  asm volatile("cp.async.wait_group 0;" ::: "memory")
#define CP_WAIT1()  asm volatile("cp.async.wait_group 1;" ::: "memory")

// ---------------- kernel 1: FUSED (xconv ∪ gateweff), handshake via g_cnt ---
// blocks 0..255: x -> padded fp16 transpose + exact rowsums, then signal
// blocks 256..383: gating (waits for rowsums) + loss + beff + Weff
#define XRS_ 4232   // half stride per smem row (xconv part)
#define MID_SMEM 43008
__global__ __launch_bounds__(512) void midfused_kernel(const float* __restrict__ x,
                                                       const float* __restrict__ w_gate,
                                                       const float* __restrict__ bias,
                                                       const float* __restrict__ W,
                                                       float* __restrict__ loss_out) {
    extern __shared__ char sm[];
    const int tid = threadIdx.x;
    const int bid = blockIdx.x;

    if (bid < 256) {
        // ================= xconv part =================
        __half* xsh = (__half*)sm;          // 4 * XRS_ halfs = 33856 B
        const int rg = bid & 15;
        const int b = bid >> 4;
        const int r0 = rg * 4;
        const int colv = tid & 15;
        const int rr = (tid >> 4) & 3;
        const int ci0 = tid >> 6;           // 0..7

        const float4* xv = (const float4*)x;
        #pragma unroll
        for (int k = 0; k < 8; k++) {
            const int ci = ci0 + 8 * k;
            const float4 v = xv[(((size_t)(b * C_ + ci) * HW_) + r0 + rr) * 16 + colv];
            // exact rowsum for (b, r0+rr, ci): reduce over 16 colv lanes
            float s = (v.x + v.y) + (v.z + v.w);
            s += __shfl_xor_sync(0xffffffffu, s, 1);
            s += __shfl_xor_sync(0xffffffffu, s, 2);
            s += __shfl_xor_sync(0xffffffffu, s, 4);
            s += __shfl_xor_sync(0xffffffffu, s, 8);
            if (colv == 0) g_rowsum[(b * 64 + r0 + rr) * C_ + ci] = s;
            const int base = rr * XRS_ + (colv * 4) * 66 + ci;
            xsh[base]       = __float2half_rn(v.x);
            xsh[base + 66]  = __float2half_rn(v.y);
            xsh[base + 132] = __float2half_rn(v.z);
            xsh[base + 198] = __float2half_rn(v.w);
        }
        __threadfence();                    // publish this thread's rowsums
        __syncthreads();                    // all block writes fenced
        if (tid == 0) atomicAdd(&g_cnt, 1); // release signal

        const uint32_t* p32 = (const uint32_t*)xsh;
        uint4* go = (uint4*)g_xT;
        for (int ou = tid; ou < 2112; ou += 512) {
            const int r = ou / 528;
            const int rem = ou - r * 528;
            const int cpg = rem >> 5;
            const int cp4 = (rem >> 3) & 3;
            const int s = rem & 7;
            const int cp = cpg * 4 + cp4;
            uint4 v = {0u, 0u, 0u, 0u};
            if (cp >= 1 && cp <= 64) {
                const int i32 = r * (XRS_ / 2) + (cp - 1) * 33 + s * 4;
                v.x = p32[i32];
                v.y = p32[i32 + 1];
                v.z = p32[i32 + 2];
                v.w = p32[i32 + 3];
            }
            const int rp = r0 + r + 1;
            go[(((size_t)b * 66 + rp) * 66 + cp) * 8 + s] = v;
        }
        if (rg == 0) {
            const uint4 z = {0u, 0u, 0u, 0u};
            for (int u = tid; u < 528; u += 512)
                go[((size_t)b * 66 * 66 + (u >> 3)) * 8 + (u & 7)] = z;
        }
        if (rg == 15) {
            const uint4 z = {0u, 0u, 0u, 0u};
            for (int u = tid; u < 528; u += 512)
                go[(((size_t)b * 66 + 65) * 66 + (u >> 3)) * 8 + (u & 7)] = z;
        }
    } else {
        // ================= gateweff part =================
        float* gx    = (float*)sm;          // 1024
        float* logit = gx + 1024;           // 256  [b*16+e]
        float* sg    = logit + 256;         // 256
        float* Wsh   = sg + 256;            // 9216 -> total 43008 B
        const int g = bid - 256;
        const int co = g >> 1;
        const int bb0 = (g & 1) * 8;
        const int b = tid >> 4, e = tid & 15;

        // stage expert weights first (independent of the handshake)
        for (int i = tid; i < E_ * 576; i += 512)
            Wsh[i] = W[(size_t)(i / 576) * (C_ * 576) + (size_t)co * 576 + (i % 576)];
        if (tid < 256) sg[tid] = 0.f;

        // acquire: wait until all 256 xconv blocks published rowsums
        if (tid == 0) {
            while (atomicAdd(&g_cnt, 0) < 256) { }
            __threadfence();
        }
        __syncthreads();

        // reduce 64 exact rowsums per (b, ci) -> gx
        for (int idx = tid; idx < B_ * C_; idx += 512) {
            const int bb = idx >> 6, ci = idx & 63;
            float s = 0.f;
            #pragma unroll 8
            for (int r = 0; r < 64; r++) s += g_rowsum[(bb * 64 + r) * C_ + ci];
            gx[idx] = s * (1.0f / (HW_ * HW_));
        }
        __syncthreads();

        if (tid < 256) {
            float s = 0.f;
            #pragma unroll 8
            for (int ci = 0; ci < C_; ci++) s += gx[b * C_ + ci] * w_gate[ci * E_ + e];
            logit[b * E_ + e] = s;
        }
        __syncthreads();

        if (tid < B_) {
            const int bb = tid;
            float mx = -1e30f;
            #pragma unroll
            for (int j = 0; j < E_; j++) mx = fmaxf(mx, logit[bb * E_ + j]);
            float p[E_]; float sum = 0.f;
            #pragma unroll
            for (int j = 0; j < E_; j++) { p[j] = __expf(logit[bb * E_ + j] - mx); sum += p[j]; }
            const float inv = 1.0f / sum;
            #pragma unroll
            for (int j = 0; j < E_; j++) p[j] *= inv;
            bool used[E_] = {false};
            float tv[KTOP_]; int ti[KTOP_]; float tsum = 0.f;
            #pragma unroll
            for (int k = 0; k < KTOP_; k++) {
                float best = -1.f; int bi = 0;
                #pragma unroll
                for (int j = 0; j < E_; j++)
                    if (!used[j] && p[j] > best) { best = p[j]; bi = j; }
                used[bi] = true; tv[k] = best; ti[k] = bi; tsum += best;
            }
            const float denom = 1.0f / (tsum + 1e-6f);
            #pragma unroll
            for (int k = 0; k < KTOP_; k++) sg[bb * E_ + ti[k]] = tv[k] * denom;
        }
        __syncthreads();

        if ((g & 1) == 0 && tid < B_) {
            float s2 = 0.f;
            #pragma unroll
            for (int ee = 0; ee < E_; ee++) s2 += sg[tid * E_ + ee] * bias[ee * C_ + co];
            g_beff[tid * C_ + co] = s2;
        }

        if (g == 0 && tid == 0) {
            float mi = 0.f, ml = 0.f, imp[E_], ld[E_];
            for (int j = 0; j < E_; j++) {
                float si = 0.f, sl = 0.f;
                for (int bb = 0; bb < B_; bb++) {
                    float gg = sg[bb * E_ + j];
                    si += gg; sl += (gg > 0.f) ? 1.f : 0.f;
                }
                imp[j] = si; ld[j] = sl; mi += si; ml += sl;
            }
            mi *= (1.0f / E_); ml *= (1.0f / E_);
            float vi = 0.f, vl = 0.f;
            for (int j = 0; j < E_; j++) {
                float di = imp[j] - mi, dl = ld[j] - ml;
                vi += di * di; vl += dl * dl;
            }
            vi *= (1.0f / (E_ - 1)); vl *= (1.0f / (E_ - 1));
            loss_out[0] = (vi / (mi * mi + 1e-10f) + vl / (ml * ml + 1e-10f)) * 0.01f;
        }

        for (int i = tid; i < 8 * 576; i += 512) {
            const int bb = bb0 + i / 576;
            const int rem = i - (i / 576) * 576;
            const int t = rem >> 6, ci = rem & 63;
            float s2 = 0.f;
            #pragma unroll
            for (int ee = 0; ee < E_; ee++) s2 += sg[bb * E_ + ee] * Wsh[ee * 576 + ci * 9 + t];
            g_Whi[(((size_t)bb * 9 + t) * C_ + co) * C_ + ci] = __float2half_rn(s2);
        }
    }
}

// ---------------- kernel 2: HMMA conv (1-pass fp16) -------------------------
#define XS_SZ   84480
#define SOP     520
#define SM_TOT  (84480 + 9 * 8192)     // 158208
__global__ __launch_bounds__(512, 1) void conv_kernel(float* __restrict__ out) {
    extern __shared__ char smem[];
    const uint32_t sb = smem_u32(smem);
    const int tid = threadIdx.x;
    const int lane = tid & 31, wid = tid >> 5;
    const int b = blockIdx.y;
    const int r0 = blockIdx.x * 8;
    const int mt = wid >> 1;
    const int nt = wid & 1;

    // reset handshake counter for the next graph replay (conv is ordered
    // after all g_cnt readers; one thread chip-wide does the write)
    if (tid == 0 && blockIdx.x == 0 && blockIdx.y == 0) g_cnt = 0;

    // ---- prologue: xs + B tap0 (group A), then B taps 1-8 (group B) --------
    {
        const uint4* xh = (const uint4*)(g_xT + (size_t)b * 66 * 66 * 64);
        for (int u = tid; u < 5280; u += 512) {
            const int q = u >> 3, s = u & 7;
            const int lr = q / 66, cp = q - lr * 66;
            const uint32_t dst = sb + (uint32_t)q * 128 +
                                 (((uint32_t)s * 16) ^ (((uint32_t)(q & 7)) << 4));
            cp_async16(dst, xh + (((size_t)(r0 + lr)) * 66 + cp) * 8 + s);
        }
        const uint4* whb = (const uint4*)(g_Whi + (size_t)b * 9 * 4096);
        {   // tap 0
            const int u = tid;
            const int co = u >> 3, s = u & 7;
            const uint32_t dst = sb + XS_SZ + (uint32_t)co * 128 +
                                 (((uint32_t)s * 16) ^ (((uint32_t)(co & 7)) << 4));
            cp_async16(dst, whb + u);
        }
        CP_COMMIT();
        for (int u = 512 + tid; u < 4608; u += 512) {
            const int v = u & 511;
            const int co = v >> 3, s = v & 7;
            const uint32_t dst = sb + XS_SZ + (uint32_t)(u >> 9) * 8192 + (uint32_t)co * 128 +
                                 (((uint32_t)s * 16) ^ (((uint32_t)(co & 7)) << 4));
            cp_async16(dst, whb + u);
        }
        CP_COMMIT();
        CP_WAIT1();
        __syncthreads();
    }

    float acc[4][4][4];
    #pragma unroll
    for (int f = 0; f < 4; f++)
        #pragma unroll
        for (int g = 0; g < 4; g++)
            #pragma unroll
            for (int k = 0; k < 4; k++) acc[f][g][k] = 0.f;

    const int pl = lane & 15;
    const uint32_t kbA = ((uint32_t)(lane >> 4)) << 4;
    const int q0 = mt * 66 + pl;
    const int rowB = nt * 32 + ((lane >> 4) << 3) + (lane & 7);
    const uint32_t kbB = ((uint32_t)((lane >> 3) & 1)) << 4;
    const uint32_t bswz = ((uint32_t)(lane & 7)) << 4;

    #pragma unroll
    for (int t = 0; t < 9; t++) {
        if (t == 1) { CP_WAIT0(); __syncthreads(); }
        const int dy = t / 3, dx = t - 3 * (t / 3);
        const int qd = q0 + dy * 66 + dx;
        const uint32_t aswz = ((uint32_t)(qd & 7)) << 4;
        const uint32_t abase = sb + (uint32_t)qd * 128;
        const uint32_t bbase = sb + XS_SZ + (uint32_t)t * 8192 + (uint32_t)rowB * 128;

        #pragma unroll
        for (int ks = 0; ks < 4; ks++) {
            const uint32_t kA = ((uint32_t)ks * 32 + kbA) ^ aswz;
            const uint32_t kB = ((uint32_t)ks * 32 + kbB) ^ bswz;
            uint32_t bf[2][4];
            ldsm_x4(bf[0], bbase + kB);
            ldsm_x4(bf[1], bbase + 2048 + kB);
            #pragma unroll
            for (int f = 0; f < 4; f++) {
                uint32_t a[4];
                ldsm_x4(a, abase + (uint32_t)f * 2048 + kA);
                mma16816(acc[f][0], a, &bf[0][0]);
                mma16816(acc[f][1], a, &bf[0][2]);
                mma16816(acc[f][2], a, &bf[1][0]);
                mma16816(acc[f][3], a, &bf[1][2]);
            }
        }
    }
    __syncthreads();

    // ---- epilogue: co-major smem -> conflict-free reads, coalesced STG -----
    float bias[4][2];
    #pragma unroll
    for (int g = 0; g < 4; g++) {
        const int c0 = nt * 32 + g * 8 + 2 * (lane & 3);
        bias[g][0] = g_beff[b * C_ + c0];
        bias[g][1] = g_beff[b * C_ + c0 + 1];
    }
    float* so = (float*)smem;
    #pragma unroll
    for (int f = 0; f < 4; f++) {
        const int p0 = mt * 64 + f * 16 + (lane >> 2);
        #pragma unroll
        for (int g = 0; g < 4; g++) {
            const int c0 = nt * 32 + g * 8 + 2 * (lane & 3);
            so[c0 * SOP + p0]           = acc[f][g][0] + bias[g][0];
            so[(c0 + 1) * SOP + p0]     = acc[f][g][1] + bias[g][1];
            so[c0 * SOP + p0 + 8]       = acc[f][g][2] + bias[g][0];
            so[(c0 + 1) * SOP + p0 + 8] = acc[f][g][3] + bias[g][1];
        }
    }
    __syncthreads();
    for (int u = tid; u < 8192; u += 512) {
        const int co = u >> 7;
        const int p4 = u & 127;
        const float4 v = *(const float4*)&so[co * SOP + 4 * p4];
        ((float4*)(out + (((size_t)b * C_ + co) * HW_ + r0) * HW_))[p4] = v;
    }
}

// ---------------- launch -----------------------------------------------------
extern "C" void kernel_launch(void* const* d_in, const int* in_sizes, int n_in,
                              void* d_out, int out_size) {
    const float* x      = (const float*)d_in[0];
    const float* w_gate = (const float*)d_in[1];
    const float* W      = (const float*)d_in[3];
    const float* bias   = (const float*)d_in[4];
    float* out = (float*)d_out;

    cudaFuncSetAttribute(conv_kernel, cudaFuncAttributeMaxDynamicSharedMemorySize, SM_TOT);

    midfused_kernel<<<384, 512, MID_SMEM>>>(x, w_gate, bias, W, out + (out_size - 1));
    conv_kernel<<<dim3(8, B_), 512, SM_TOT>>>(out);
}

// round 14
// speedup vs baseline: 1.7603x; 1.7603x over previous
#include <cuda_runtime.h>
#include <cuda_fp16.h>
#include <math.h>
#include <stdint.h>

#define B_ 16
#define C_ 64
#define HW_ 64
#define E_ 16
#define KTOP_ 4

// ------------------------- scratch (device globals) -------------------------
__device__ float g_gx[B_ * C_];                     // per-(b,ci) means
__device__ int   g_cnt = 0;                         // mean-done counter (64)
__device__ float g_beff[B_ * C_];
__device__ __half g_Whi[B_ * 9 * C_ * C_];          // [b][tap][co][ci]
__device__ __half g_xT[(size_t)B_ * 66 * 66 * C_];  // [b][rp][cp][ci]

// ------------------------- helpers ------------------------------------------
__device__ __forceinline__ uint32_t smem_u32(const void* p) {
    uint32_t a;
    asm("{ .reg .u64 t; cvta.to.shared.u64 t, %1; cvt.u32.u64 %0, t; }" : "=r"(a) : "l"(p));
    return a;
}
__device__ __forceinline__ void ldsm_x4(uint32_t* r, uint32_t addr) {
    asm volatile("ldmatrix.sync.aligned.m8n8.x4.shared.b16 {%0,%1,%2,%3}, [%4];"
        : "=r"(r[0]), "=r"(r[1]), "=r"(r[2]), "=r"(r[3]) : "r"(addr));
}
__device__ __forceinline__ void mma16816(float* d, const uint32_t* a, const uint32_t* b) {
    asm volatile(
        "mma.sync.aligned.m16n8k16.row.col.f32.f16.f16.f32 "
        "{%0,%1,%2,%3}, {%4,%5,%6,%7}, {%8,%9}, {%0,%1,%2,%3};"
        : "+f"(d[0]), "+f"(d[1]), "+f"(d[2]), "+f"(d[3])
        : "r"(a[0]), "r"(a[1]), "r"(a[2]), "r"(a[3]), "r"(b[0]), "r"(b[1]));
}
__device__ __forceinline__ void cp_async16(uint32_t dst, const void* src) {
    asm volatile("cp.async.cg.shared.global [%0], [%1], 16;" :: "r"(dst), "l"(src));
}
#define CP_COMMIT() asm volatile("cp.async.commit_group;" ::: "memory")
#define CP_WAIT0()  asm volatile("cp.async.wait_group 0;" ::: "memory")
#define CP_WAIT1()  asm volatile("cp.async.wait_group 1;" ::: "memory")

// ---------------- kernel 1: FUSED (xconv ∪ mean ∪ gateweff) -----------------
// blocks 0..255   : x -> padded fp16 transpose (rg = bid&15, b = bid>>4)
// blocks 256..319 : gate means (16 warps x 1 plane each), release g_cnt
// blocks 320..447 : gating (waits on g_cnt==64) + loss + beff + Weff
#define XRS_ 4232   // half stride per smem row (xconv part)
#define MID_SMEM 43008
__global__ __launch_bounds__(512) void midfused_kernel(const float* __restrict__ x,
                                                       const float* __restrict__ w_gate,
                                                       const float* __restrict__ bias,
                                                       const float* __restrict__ W,
                                                       float* __restrict__ loss_out) {
    extern __shared__ char sm[];
    const int tid = threadIdx.x;
    const int bid = blockIdx.x;

    if (bid < 256) {
        // ================= xconv part =================
        __half* xsh = (__half*)sm;          // 4 * XRS_ halfs = 33856 B
        const int rg = bid & 15;
        const int b = bid >> 4;
        const int r0 = rg * 4;
        const int colv = tid & 15;
        const int rr = (tid >> 4) & 3;
        const int ci0 = tid >> 6;           // 0..7

        const float4* xv = (const float4*)x;
        #pragma unroll
        for (int k = 0; k < 8; k++) {
            const int ci = ci0 + 8 * k;
            const float4 v = xv[(((size_t)(b * C_ + ci) * HW_) + r0 + rr) * 16 + colv];
            const int base = rr * XRS_ + (colv * 4) * 66 + ci;
            xsh[base]       = __float2half_rn(v.x);
            xsh[base + 66]  = __float2half_rn(v.y);
            xsh[base + 132] = __float2half_rn(v.z);
            xsh[base + 198] = __float2half_rn(v.w);
        }
        __syncthreads();

        const uint32_t* p32 = (const uint32_t*)xsh;
        uint4* go = (uint4*)g_xT;
        for (int ou = tid; ou < 2112; ou += 512) {
            const int r = ou / 528;
            const int rem = ou - r * 528;
            const int cpg = rem >> 5;
            const int cp4 = (rem >> 3) & 3;
            const int s = rem & 7;
            const int cp = cpg * 4 + cp4;
            uint4 v = {0u, 0u, 0u, 0u};
            if (cp >= 1 && cp <= 64) {
                const int i32 = r * (XRS_ / 2) + (cp - 1) * 33 + s * 4;
                v.x = p32[i32];
                v.y = p32[i32 + 1];
                v.z = p32[i32 + 2];
                v.w = p32[i32 + 3];
            }
            const int rp = r0 + r + 1;
            go[(((size_t)b * 66 + rp) * 66 + cp) * 8 + s] = v;
        }
        if (rg == 0) {
            const uint4 z = {0u, 0u, 0u, 0u};
            for (int u = tid; u < 528; u += 512)
                go[((size_t)b * 66 * 66 + (u >> 3)) * 8 + (u & 7)] = z;
        }
        if (rg == 15) {
            const uint4 z = {0u, 0u, 0u, 0u};
            for (int u = tid; u < 528; u += 512)
                go[(((size_t)b * 66 + 65) * 66 + (u >> 3)) * 8 + (u & 7)] = z;
        }
    } else if (bid < 320) {
        // ================= mean part (64 blocks x 16 warps) =================
        const int w = tid >> 5, lane = tid & 31;
        const int p = (bid - 256) * 16 + w;            // plane (b*64+ci), 0..1023
        const float4* pp = (const float4*)(x + (size_t)p * (HW_ * HW_));
        float s = 0.f;
        #pragma unroll
        for (int j = 0; j < 32; j++) {                 // 1024 float4 / 32 lanes
            const float4 v = pp[lane + 32 * j];
            s += (v.x + v.y) + (v.z + v.w);
        }
        #pragma unroll
        for (int o = 16; o > 0; o >>= 1) s += __shfl_xor_sync(0xffffffffu, s, o);
        if (lane == 0) {
            g_gx[p] = s * (1.0f / (HW_ * HW_));
            __threadfence();                           // release this warp's write
        }
        __syncthreads();
        if (tid == 0) atomicAdd(&g_cnt, 1);            // signal (64 total)
    } else {
        // ================= gateweff part =================
        float* gx    = (float*)sm;          // 1024
        float* logit = gx + 1024;           // 256  [b*16+e]
        float* sg    = logit + 256;         // 256
        float* Wsh   = sg + 256;            // 9216 -> total 43008 B
        const int g = bid - 320;
        const int co = g >> 1;
        const int bb0 = (g & 1) * 8;
        const int b = tid >> 4, e = tid & 15;

        // stage expert weights first (independent of the handshake)
        for (int i = tid; i < E_ * 576; i += 512)
            Wsh[i] = W[(size_t)(i / 576) * (C_ * 576) + (size_t)co * 576 + (i % 576)];
        if (tid < 256) sg[tid] = 0.f;

        // acquire: wait until all 64 mean blocks have signaled
        if (tid == 0) {
            while (*((volatile int*)&g_cnt) < 64) __nanosleep(64);
            __threadfence();                           // acquire
        }
        __syncthreads();

        for (int i = tid; i < B_ * C_; i += 512) gx[i] = g_gx[i];
        __syncthreads();

        if (tid < 256) {
            float s = 0.f;
            #pragma unroll 8
            for (int ci = 0; ci < C_; ci++) s += gx[b * C_ + ci] * w_gate[ci * E_ + e];
            logit[b * E_ + e] = s;
        }
        __syncthreads();

        if (tid < B_) {
            const int bb = tid;
            float mx = -1e30f;
            #pragma unroll
            for (int j = 0; j < E_; j++) mx = fmaxf(mx, logit[bb * E_ + j]);
            float p[E_]; float sum = 0.f;
            #pragma unroll
            for (int j = 0; j < E_; j++) { p[j] = __expf(logit[bb * E_ + j] - mx); sum += p[j]; }
            const float inv = 1.0f / sum;
            #pragma unroll
            for (int j = 0; j < E_; j++) p[j] *= inv;
            bool used[E_] = {false};
            float tv[KTOP_]; int ti[KTOP_]; float tsum = 0.f;
            #pragma unroll
            for (int k = 0; k < KTOP_; k++) {
                float best = -1.f; int bi = 0;
                #pragma unroll
                for (int j = 0; j < E_; j++)
                    if (!used[j] && p[j] > best) { best = p[j]; bi = j; }
                used[bi] = true; tv[k] = best; ti[k] = bi; tsum += best;
            }
            const float denom = 1.0f / (tsum + 1e-6f);
            #pragma unroll
            for (int k = 0; k < KTOP_; k++) sg[bb * E_ + ti[k]] = tv[k] * denom;
        }
        __syncthreads();

        if ((g & 1) == 0 && tid < B_) {
            float s2 = 0.f;
            #pragma unroll
            for (int ee = 0; ee < E_; ee++) s2 += sg[tid * E_ + ee] * bias[ee * C_ + co];
            g_beff[tid * C_ + co] = s2;
        }

        if (g == 0 && tid == 0) {
            float mi = 0.f, ml = 0.f, imp[E_], ld[E_];
            for (int j = 0; j < E_; j++) {
                float si = 0.f, sl = 0.f;
                for (int bb = 0; bb < B_; bb++) {
                    float gg = sg[bb * E_ + j];
                    si += gg; sl += (gg > 0.f) ? 1.f : 0.f;
                }
                imp[j] = si; ld[j] = sl; mi += si; ml += sl;
            }
            mi *= (1.0f / E_); ml *= (1.0f / E_);
            float vi = 0.f, vl = 0.f;
            for (int j = 0; j < E_; j++) {
                float di = imp[j] - mi, dl = ld[j] - ml;
                vi += di * di; vl += dl * dl;
            }
            vi *= (1.0f / (E_ - 1)); vl *= (1.0f / (E_ - 1));
            loss_out[0] = (vi / (mi * mi + 1e-10f) + vl / (ml * ml + 1e-10f)) * 0.01f;
        }

        for (int i = tid; i < 8 * 576; i += 512) {
            const int bb = bb0 + i / 576;
            const int rem = i - (i / 576) * 576;
            const int t = rem >> 6, ci = rem & 63;
            float s2 = 0.f;
            #pragma unroll
            for (int ee = 0; ee < E_; ee++) s2 += sg[bb * E_ + ee] * Wsh[ee * 576 + ci * 9 + t];
            g_Whi[(((size_t)bb * 9 + t) * C_ + co) * C_ + ci] = __float2half_rn(s2);
        }
    }
}

// ---------------- kernel 2: HMMA conv (1-pass fp16) -------------------------
#define XS_SZ   84480
#define SOP     520
#define SM_TOT  (84480 + 9 * 8192)     // 158208
__global__ __launch_bounds__(512, 1) void conv_kernel(float* __restrict__ out) {
    extern __shared__ char smem[];
    const uint32_t sb = smem_u32(smem);
    const int tid = threadIdx.x;
    const int lane = tid & 31, wid = tid >> 5;
    const int b = blockIdx.y;
    const int r0 = blockIdx.x * 8;
    const int mt = wid >> 1;
    const int nt = wid & 1;

    // reset handshake counter for the next replay (conv is ordered after all
    // g_cnt readers; one thread chip-wide)
    if (tid == 0 && blockIdx.x == 0 && blockIdx.y == 0) g_cnt = 0;

    // ---- prologue: xs + B tap0 (group A), then B taps 1-8 (group B) --------
    {
        const uint4* xh = (const uint4*)(g_xT + (size_t)b * 66 * 66 * 64);
        for (int u = tid; u < 5280; u += 512) {
            const int q = u >> 3, s = u & 7;
            const int lr = q / 66, cp = q - lr * 66;
            const uint32_t dst = sb + (uint32_t)q * 128 +
                                 (((uint32_t)s * 16) ^ (((uint32_t)(q & 7)) << 4));
            cp_async16(dst, xh + (((size_t)(r0 + lr)) * 66 + cp) * 8 + s);
        }
        const uint4* whb = (const uint4*)(g_Whi + (size_t)b * 9 * 4096);
        {   // tap 0
            const int u = tid;
            const int co = u >> 3, s = u & 7;
            const uint32_t dst = sb + XS_SZ + (uint32_t)co * 128 +
                                 (((uint32_t)s * 16) ^ (((uint32_t)(co & 7)) << 4));
            cp_async16(dst, whb + u);
        }
        CP_COMMIT();
        for (int u = 512 + tid; u < 4608; u += 512) {
            const int v = u & 511;
            const int co = v >> 3, s = v & 7;
            const uint32_t dst = sb + XS_SZ + (uint32_t)(u >> 9) * 8192 + (uint32_t)co * 128 +
                                 (((uint32_t)s * 16) ^ (((uint32_t)(co & 7)) << 4));
            cp_async16(dst, whb + u);
        }
        CP_COMMIT();
        CP_WAIT1();
        __syncthreads();
    }

    float acc[4][4][4];
    #pragma unroll
    for (int f = 0; f < 4; f++)
        #pragma unroll
        for (int g = 0; g < 4; g++)
            #pragma unroll
            for (int k = 0; k < 4; k++) acc[f][g][k] = 0.f;

    const int pl = lane & 15;
    const uint32_t kbA = ((uint32_t)(lane >> 4)) << 4;
    const int q0 = mt * 66 + pl;
    const int rowB = nt * 32 + ((lane >> 4) << 3) + (lane & 7);
    const uint32_t kbB = ((uint32_t)((lane >> 3) & 1)) << 4;
    const uint32_t bswz = ((uint32_t)(lane & 7)) << 4;

    #pragma unroll
    for (int t = 0; t < 9; t++) {
        if (t == 1) { CP_WAIT0(); __syncthreads(); }
        const int dy = t / 3, dx = t - 3 * (t / 3);
        const int qd = q0 + dy * 66 + dx;
        const uint32_t aswz = ((uint32_t)(qd & 7)) << 4;
        const uint32_t abase = sb + (uint32_t)qd * 128;
        const uint32_t bbase = sb + XS_SZ + (uint32_t)t * 8192 + (uint32_t)rowB * 128;

        #pragma unroll
        for (int ks = 0; ks < 4; ks++) {
            const uint32_t kA = ((uint32_t)ks * 32 + kbA) ^ aswz;
            const uint32_t kB = ((uint32_t)ks * 32 + kbB) ^ bswz;
            uint32_t bf[2][4];
            ldsm_x4(bf[0], bbase + kB);
            ldsm_x4(bf[1], bbase + 2048 + kB);
            #pragma unroll
            for (int f = 0; f < 4; f++) {
                uint32_t a[4];
                ldsm_x4(a, abase + (uint32_t)f * 2048 + kA);
                mma16816(acc[f][0], a, &bf[0][0]);
                mma16816(acc[f][1], a, &bf[0][2]);
                mma16816(acc[f][2], a, &bf[1][0]);
                mma16816(acc[f][3], a, &bf[1][2]);
            }
        }
    }
    __syncthreads();

    // ---- epilogue: co-major smem -> conflict-free reads, coalesced STG -----
    float bias[4][2];
    #pragma unroll
    for (int g = 0; g < 4; g++) {
        const int c0 = nt * 32 + g * 8 + 2 * (lane & 3);
        bias[g][0] = g_beff[b * C_ + c0];
        bias[g][1] = g_beff[b * C_ + c0 + 1];
    }
    float* so = (float*)smem;
    #pragma unroll
    for (int f = 0; f < 4; f++) {
        const int p0 = mt * 64 + f * 16 + (lane >> 2);
        #pragma unroll
        for (int g = 0; g < 4; g++) {
            const int c0 = nt * 32 + g * 8 + 2 * (lane & 3);
            so[c0 * SOP + p0]           = acc[f][g][0] + bias[g][0];
            so[(c0 + 1) * SOP + p0]     = acc[f][g][1] + bias[g][1];
            so[c0 * SOP + p0 + 8]       = acc[f][g][2] + bias[g][0];
            so[(c0 + 1) * SOP + p0 + 8] = acc[f][g][3] + bias[g][1];
        }
    }
    __syncthreads();
    for (int u = tid; u < 8192; u += 512) {
        const int co = u >> 7;
        const int p4 = u & 127;
        const float4 v = *(const float4*)&so[co * SOP + 4 * p4];
        ((float4*)(out + (((size_t)b * C_ + co) * HW_ + r0) * HW_))[p4] = v;
    }
}

// ---------------- launch -----------------------------------------------------
extern "C" void kernel_launch(void* const* d_in, const int* in_sizes, int n_in,
                              void* d_out, int out_size) {
    const float* x      = (const float*)d_in[0];
    const float* w_gate = (const float*)d_in[1];
    const float* W      = (const float*)d_in[3];
    const float* bias   = (const float*)d_in[4];
    float* out = (float*)d_out;

    cudaFuncSetAttribute(conv_kernel, cudaFuncAttributeMaxDynamicSharedMemorySize, SM_TOT);

    midfused_kernel<<<448, 512, MID_SMEM>>>(x, w_gate, bias, W, out + (out_size - 1));
    conv_kernel<<<dim3(8, B_), 512, SM_TOT>>>(out);
}